// round 6
// baseline (speedup 1.0000x reference)
#include <cuda_runtime.h>
#include <math.h>

#define BATCH 256
#define TLEN  50
#define NOBS  8192
#define NKC   50

// ---- device-global scratch (no allocations allowed) ----
__device__ unsigned char g_assign[NOBS];                 // assign[] as uint8
__device__ float         g_probs_scratch[BATCH * TLEN];  // fallback sink

// ============================================================
// k1: recover assign[] from one-hot A. Two independent float4
// loads per thread (MLP=2), 200 blocks x 256.
// ============================================================
__global__ __launch_bounds__(256)
void k1_prep(const float4* __restrict__ A4) {
    const int half = NOBS * NKC / 8;              // 51200 float4s per half
    int idx = blockIdx.x * 256 + threadIdx.x;
    float4 v0 = A4[idx];
    float4 v1 = A4[idx + half];

    int b0 = idx * 4;
    if (v0.x > 0.5f) { int i = b0 + 0; g_assign[i / NKC] = (unsigned char)(i % NKC); }
    if (v0.y > 0.5f) { int i = b0 + 1; g_assign[i / NKC] = (unsigned char)(i % NKC); }
    if (v0.z > 0.5f) { int i = b0 + 2; g_assign[i / NKC] = (unsigned char)(i % NKC); }
    if (v0.w > 0.5f) { int i = b0 + 3; g_assign[i / NKC] = (unsigned char)(i % NKC); }

    int b1 = (idx + half) * 4;
    if (v1.x > 0.5f) { int i = b1 + 0; g_assign[i / NKC] = (unsigned char)(i % NKC); }
    if (v1.y > 0.5f) { int i = b1 + 1; g_assign[i / NKC] = (unsigned char)(i % NKC); }
    if (v1.z > 0.5f) { int i = b1 + 2; g_assign[i / NKC] = (unsigned char)(i % NKC); }
    if (v1.w > 0.5f) { int i = b1 + 3; g_assign[i / NKC] = (unsigned char)(i % NKC); }
}

// ============================================================
// k2: fused BKT via Moebius-matrix reformulation + expansion.
// One block per batch row. Each step t is a Moebius map
// s -> (A s + B)/(C s + D) on KC ap_t; maps compose via 2x2
// matrix products. out[t] and final state[k] are computed by
// INDEPENDENT threads (no serial 49-step chain):
//   warps 0-1: thread t composes {M_i : i<=t, ap_i==ck_t}
//   warps 2-3: thread k composes {M_i : ap_i==k}
// ============================================================
__global__ __launch_bounds__(128, 8)
void k2_fused(const int*   __restrict__ prev_kc,
              const int*   __restrict__ curr_kc,
              const float* __restrict__ prev_corr,
              const float* __restrict__ kc_logits,
              float*       __restrict__ probs_out,
              float*       __restrict__ state_out,
              int do_state) {
    __shared__ unsigned char s_assign[NOBS];   // 8 KB
    __shared__ float4        s_pr[NKC];        // sigmoid(pl,pf,p2,p3)
    __shared__ float         s_p4[NKC];        // initial state per KC
    __shared__ float         s_state[NKC];     // final compact state
    __shared__ float4        s_M[TLEN];        // Moebius matrix per step
    __shared__ unsigned char s_ap[TLEN];       // assign[pk_t]
    __shared__ unsigned char s_ack[TLEN];      // assign[ck_t]

    const int b   = blockIdx.x;
    const int tid = threadIdx.x;

    // --- copy g_assign -> shared (L2-hot, coalesced int4) ---
    {
        const int4* src = (const int4*)g_assign;
        int4*       dst = (int4*)s_assign;
        #pragma unroll
        for (int i = 0; i < 4; i++) dst[tid + 128 * i] = src[tid + 128 * i];
    }

    // --- row inputs + sigmoids (threads 0..49), overlap the copy ---
    int   pk = 0, ck = 0;
    float cr = 0.0f;
    if (tid < TLEN) {
        pk = prev_kc[b * TLEN + tid];
        ck = curr_kc[b * TLEN + tid];
        cr = prev_corr[b * TLEN + tid];

        float4 p;
        p.x = 1.0f / (1.0f + __expf(-kc_logits[tid * 5 + 0]));
        p.y = 1.0f / (1.0f + __expf(-kc_logits[tid * 5 + 1]));
        p.z = 1.0f / (1.0f + __expf(-kc_logits[tid * 5 + 2]));
        p.w = 1.0f / (1.0f + __expf(-kc_logits[tid * 5 + 3]));
        s_pr[tid] = p;
        s_p4[tid] = 1.0f / (1.0f + __expf(-kc_logits[tid * 5 + 4]));
    }
    __syncthreads();   // s_assign + s_pr/s_p4 complete

    // --- resolve indices and build per-step Moebius matrices ---
    if (tid < TLEN) {
        int ap = s_assign[pk];
        s_ap[tid]  = (unsigned char)ap;
        s_ack[tid] = s_assign[ck];

        float4 pp = s_pr[ap];
        float o0, o1;
        if (cr > 0.5f) { o0 = pp.z;        o1 = pp.w;        }
        else           { o0 = 1.0f - pp.z; o1 = 1.0f - pp.w; }
        float d10 = o1 - o0;
        float c1  = 1.0f - pp.y - pp.x;    // (1-pf) - pl
        // pred = (A*ss + B) / (C*ss + D)
        s_M[tid] = make_float4(fmaf(pp.x, d10, c1 * o1),  // A
                               pp.x * o0,                  // B
                               d10,                        // C
                               o0);                        // D
    }
    __syncthreads();

    if (tid < TLEN) {
        // ---- pass A: out[t] (threads 0..49, t = tid) ----
        const int t = tid;
        const int k = s_ack[t];
        float a = 1.0f, bb = 0.0f, c = 0.0f, d = 1.0f;
        #pragma unroll 1
        for (int i = 1; i < TLEN; i++) {
            float4 M = s_M[i];                    // broadcast LDS
            if (i <= t && (int)s_ap[i] == k) {    // compose: new = M * cur
                float na = fmaf(M.x, a,  M.y * c);
                float nb = fmaf(M.x, bb, M.y * d);
                float nc = fmaf(M.z, a,  M.w * c);
                float nd = fmaf(M.z, bb, M.w * d);
                a = na; bb = nb; c = nc; d = nd;
            }
        }
        float s0 = s_p4[k];
        float sf = __fdividef(fmaf(a, s0, bb), fmaf(c, s0, d));
        float4 pc = s_pr[k];
        probs_out[b * TLEN + t] = fmaf(pc.w - pc.z, sf, pc.z);
    } else if (tid >= 64 && tid < 64 + NKC) {
        // ---- pass B: final state[k] (threads 64..113, k = tid-64) ----
        const int k = tid - 64;
        float a = 1.0f, bb = 0.0f, c = 0.0f, d = 1.0f;
        #pragma unroll 1
        for (int i = 1; i < TLEN; i++) {
            float4 M = s_M[i];
            if ((int)s_ap[i] == k) {
                float na = fmaf(M.x, a,  M.y * c);
                float nb = fmaf(M.x, bb, M.y * d);
                float nc = fmaf(M.z, a,  M.w * c);
                float nd = fmaf(M.z, bb, M.w * d);
                a = na; bb = nb; c = nc; d = nd;
            }
        }
        float s0 = s_p4[k];
        s_state[k] = __fdividef(fmaf(a, s0, bb), fmaf(c, s0, d));
    }
    __syncthreads();   // s_state final

    // --- expand final state to (1, NOBS): 16 float4 stores/thread ---
    if (do_state) {
        float4*       o  = (float4*)(state_out + (size_t)b * NOBS);
        const uchar4* a4 = (const uchar4*)s_assign;
        #pragma unroll
        for (int i = 0; i < 16; i++) {
            uchar4 a = a4[tid + 128 * i];
            o[tid + 128 * i] =
                make_float4(s_state[a.x], s_state[a.y], s_state[a.z], s_state[a.w]);
        }
    }
}

// ============================================================
extern "C" void kernel_launch(void* const* d_in, const int* in_sizes, int n_in,
                              void* d_out, int out_size) {
    const int*    prev_kc   = (const int*)   d_in[0];
    const int*    curr_kc   = (const int*)   d_in[1];
    const float*  prev_corr = (const float*) d_in[2];
    const float*  kc_logits = (const float*) d_in[3];
    const float4* A4        = (const float4*)d_in[4];
    float*        out       = (float*)d_out;

    k1_prep<<<(NOBS * NKC / 8) / 256, 256>>>(A4);

    // Output layout: [probs (256*50) | state (256*8192)] concatenated.
    float* probs_out = out;
    float* state_out = out + BATCH * TLEN;
    int    do_state  = 1;

    if (out_size == BATCH * TLEN) {
        do_state  = 0;
        state_out = out;                 // unused
    } else if (out_size == BATCH * NOBS) {
        void* scratch = nullptr;
        cudaGetSymbolAddress(&scratch, g_probs_scratch);
        probs_out = (float*)scratch;
        state_out = out;
    }

    k2_fused<<<BATCH, 128>>>(prev_kc, curr_kc, prev_corr, kc_logits,
                             probs_out, state_out, do_state);
}